// round 11
// baseline (speedup 1.0000x reference)
#include <cuda_runtime.h>
#include <cuda_bf16.h>
#include <cuda_fp16.h>
#include <math_constants.h>
#include <cstdint>

// ---------------- problem constants ----------------
#define N_NODES 20000
#define N_EDGES 320000
#define F_IN    256
#define HIDC    64
#define HEADS   8
#define NCLS    64
#define HC1     (HEADS*HIDC)      // 512
#define NEG_SLOPE 0.2f
#define SM_EPS  1e-16f

typedef unsigned long long u64;

// ---------------- scratch (static device globals; no allocs) ----------------
__device__ __half g_xl1h[(size_t)N_NODES * 512];   // xl1 fp16 (gathered per edge)
__device__ float  g_xr1 [(size_t)N_NODES * 512];   // xr1 fp32 (read once per node)
__device__ __half g_xl2h[(size_t)N_NODES * 64];    // xl2 fp16
__device__ float  g_xr2 [(size_t)N_NODES * 64];    // xr2 fp32
__device__ int   g_deg[N_NODES];
__device__ int   g_off[N_NODES + 1];
__device__ int   g_cur[N_NODES];
__device__ int   g_esrc[N_EDGES];                  // CSR-ordered source node ids

// bf16 split operands
__device__ __nv_bfloat16 g_xhi[(size_t)N_NODES * F_IN];
__device__ __nv_bfloat16 g_xlo[(size_t)N_NODES * F_IN];
__device__ __nv_bfloat16 g_hhi[(size_t)N_NODES * HC1];   // written by node1 epilogue
__device__ __nv_bfloat16 g_hlo[(size_t)N_NODES * HC1];
__device__ __nv_bfloat16 g_wt1hi[1024 * 256];   // [Ntot=1024][K=256] (W^T, K-contig)
__device__ __nv_bfloat16 g_wt1lo[1024 * 256];
__device__ __nv_bfloat16 g_wt2hi[128 * 512];    // [Ntot=128][K=512]
__device__ __nv_bfloat16 g_wt2lo[128 * 512];

// ---------------- helpers ----------------
__device__ __forceinline__ uint32_t smem_u32(const void* p) {
    uint32_t a;
    asm("{ .reg .u64 t; cvta.to.shared.u64 t, %1; cvt.u32.u64 %0, t; }" : "=r"(a) : "l"(p));
    return a;
}
#define SWZ128(o) ((o) ^ (((o) >> 3) & 0x70))

__device__ __forceinline__ void cp16(uint32_t dst, const void* src) {
    asm volatile("cp.async.cg.shared.global [%0], [%1], 16;" :: "r"(dst), "l"(src));
}
__device__ __forceinline__ void cp_commit() {
    asm volatile("cp.async.commit_group;" ::: "memory");
}
template <int N>
__device__ __forceinline__ void cp_wait() {
    asm volatile("cp.async.wait_group %0;" :: "n"(N) : "memory");
}

__device__ __forceinline__ void ldmx4(uint32_t* r, uint32_t addr) {
    asm volatile("ldmatrix.sync.aligned.m8n8.x4.shared.b16 {%0,%1,%2,%3}, [%4];"
                 : "=r"(r[0]), "=r"(r[1]), "=r"(r[2]), "=r"(r[3]) : "r"(addr));
}
__device__ __forceinline__ void mma16816(float* c, const uint32_t* a, uint32_t b0, uint32_t b1) {
    asm volatile("mma.sync.aligned.m16n8k16.row.col.f32.bf16.bf16.f32 "
                 "{%0,%1,%2,%3}, {%4,%5,%6,%7}, {%8,%9}, {%0,%1,%2,%3};"
                 : "+f"(c[0]), "+f"(c[1]), "+f"(c[2]), "+f"(c[3])
                 : "r"(a[0]), "r"(a[1]), "r"(a[2]), "r"(a[3]), "r"(b0), "r"(b1));
}

// ---------------- CSR build ----------------
__global__ void hist_kernel(const int* __restrict__ dst) {
    int e = blockIdx.x * blockDim.x + threadIdx.x;
    if (e < N_EDGES) atomicAdd(&g_deg[dst[e]], 1);
}

__global__ void scan_kernel() {
    __shared__ int sums[1024];
    const int CH = (N_NODES + 1023) / 1024;
    int t = threadIdx.x;
    int base = t * CH;
    int s = 0;
    for (int i = 0; i < CH; i++) {
        int idx = base + i;
        if (idx < N_NODES) s += g_deg[idx];
    }
    sums[t] = s;
    __syncthreads();
    for (int d = 1; d < 1024; d <<= 1) {
        int v = (t >= d) ? sums[t - d] : 0;
        __syncthreads();
        sums[t] += v;
        __syncthreads();
    }
    int pre = (t == 0) ? 0 : sums[t - 1];
    for (int i = 0; i < CH; i++) {
        int idx = base + i;
        if (idx < N_NODES) {
            g_off[idx] = pre;
            g_cur[idx] = pre;
            pre += g_deg[idx];
        }
    }
    if (t == 0) g_off[N_NODES] = sums[1023];
}

__global__ void scatter_kernel(const int* __restrict__ src, const int* __restrict__ dst) {
    int e = blockIdx.x * blockDim.x + threadIdx.x;
    if (e < N_EDGES) {
        int p = atomicAdd(&g_cur[dst[e]], 1);
        g_esrc[p] = src[e];
    }
}

// ---------------- bf16 split kernels ----------------
__global__ void split_kernel(const float* __restrict__ src,
                             __nv_bfloat16* __restrict__ hi,
                             __nv_bfloat16* __restrict__ lo, int n) {
    int i = blockIdx.x * blockDim.x + threadIdx.x;
    if (i < n) {
        float v = src[i];
        __nv_bfloat16 h = __float2bfloat16(v);
        hi[i] = h;
        lo[i] = __float2bfloat16(v - __bfloat162float(h));
    }
}

// W0,W1: [K, N0] row-major each -> Wt [2*N0, K]
__global__ void wtsplit_kernel(const float* __restrict__ W0, const float* __restrict__ W1,
                               int K, int N0,
                               __nv_bfloat16* __restrict__ hi,
                               __nv_bfloat16* __restrict__ lo) {
    int i = blockIdx.x * blockDim.x + threadIdx.x;
    if (i >= 2 * N0 * K) return;
    int n = i / K, k = i % K;
    float v = (n < N0) ? W0[(size_t)k * N0 + n] : W1[(size_t)k * N0 + (n - N0)];
    __nv_bfloat16 h = __float2bfloat16(v);
    hi[(size_t)n * K + k] = h;
    lo[(size_t)n * K + k] = __float2bfloat16(v - __bfloat162float(h));
}

// ---------------- mma.sync split-bf16 GEMM, cp.async double-buffered ----------------
// Columns [0,nx) -> fp16 output Ch (ld nx); columns [nx,2nx) -> fp32 output Cf (ld nx).
#define BUF_AHI 0
#define BUF_ALO 16384
#define BUF_BHI 32768
#define BUF_BLO 40960
#define BUF_SZ  49152
#define SM_TOT  (2 * BUF_SZ)

__global__ void __launch_bounds__(256) gemm_mma_kernel(
    int M, int K, int nx,
    const __nv_bfloat16* __restrict__ Ahi, const __nv_bfloat16* __restrict__ Alo,
    const __nv_bfloat16* __restrict__ Bhi, const __nv_bfloat16* __restrict__ Blo,
    __half* __restrict__ Ch, float* __restrict__ Cf)
{
    extern __shared__ char smem[];
    uint32_t sb = smem_u32(smem);
    const int tid = threadIdx.x, wid = tid >> 5, lane = tid & 31;
    const int by = blockIdx.y, bx = blockIdx.x;
    const int warpM = wid & 3, warpN = wid >> 2;

    float acc[2][4][4];
#pragma unroll
    for (int a = 0; a < 2; a++)
#pragma unroll
        for (int b = 0; b < 4; b++)
#pragma unroll
            for (int c = 0; c < 4; c++) acc[a][b][c] = 0.f;

    const int nchunks = K >> 6;

    auto issue = [&](int ch) {
        uint32_t buf = sb + (uint32_t)(ch & 1) * BUF_SZ;
        int k0 = ch << 6;
#pragma unroll
        for (int it = 0; it < 4; it++) {
            int i = tid + 256 * it;
            int row = i >> 3, g = (i & 7) << 3;
            int gr = by * 128 + row;
            if (gr >= M) gr = M - 1;
            uint32_t so = SWZ128(row * 128 + g * 2);
            cp16(buf + BUF_AHI + so, Ahi + (size_t)gr * K + k0 + g);
            cp16(buf + BUF_ALO + so, Alo + (size_t)gr * K + k0 + g);
        }
#pragma unroll
        for (int it = 0; it < 2; it++) {
            int i = tid + 256 * it;
            int row = i >> 3, g = (i & 7) << 3;
            int gn = bx * 64 + row;
            uint32_t so = SWZ128(row * 128 + g * 2);
            cp16(buf + BUF_BHI + so, Bhi + (size_t)gn * K + k0 + g);
            cp16(buf + BUF_BLO + so, Blo + (size_t)gn * K + k0 + g);
        }
        cp_commit();
    };

    issue(0);
    for (int ch = 0; ch < nchunks; ch++) {
        if (ch + 1 < nchunks) {
            issue(ch + 1);
            cp_wait<1>();
        } else {
            cp_wait<0>();
        }
        __syncthreads();

        uint32_t buf = sb + (uint32_t)(ch & 1) * BUF_SZ;
#pragma unroll
        for (int ks = 0; ks < 4; ks++) {
            uint32_t ahi[2][4], alo[2][4], bhi[2][4], blo[2][4];
            int colb = ks * 32 + (lane >> 4) * 16;
#pragma unroll
            for (int mt = 0; mt < 2; mt++) {
                uint32_t off = SWZ128((warpM * 32 + mt * 16 + (lane & 15)) * 128 + colb);
                ldmx4(ahi[mt], buf + BUF_AHI + off);
                ldmx4(alo[mt], buf + BUF_ALO + off);
            }
#pragma unroll
            for (int nt = 0; nt < 2; nt++) {
                uint32_t off = SWZ128((warpN * 32 + nt * 16 + (lane & 15)) * 128 + colb);
                ldmx4(bhi[nt], buf + BUF_BHI + off);
                ldmx4(blo[nt], buf + BUF_BLO + off);
            }
#pragma unroll
            for (int mt = 0; mt < 2; mt++)
#pragma unroll
                for (int nt = 0; nt < 2; nt++)
#pragma unroll
                    for (int hf = 0; hf < 2; hf++) {
                        float* c = acc[mt][nt * 2 + hf];
                        mma16816(c, ahi[mt], bhi[nt][hf], bhi[nt][hf + 2]);
                        mma16816(c, ahi[mt], blo[nt][hf], blo[nt][hf + 2]);
                        mma16816(c, alo[mt], bhi[nt][hf], bhi[nt][hf + 2]);
                    }
        }
        __syncthreads();
    }

    float* stage = (float*)smem;
    {
        int r0 = lane >> 2, cb = (lane & 3) * 2;
#pragma unroll
        for (int mt = 0; mt < 2; mt++)
#pragma unroll
            for (int j = 0; j < 4; j++) {
                int col = warpN * 32 + (j >> 1) * 16 + (j & 1) * 8 + cb;
                float* st = stage + (warpM * 32 + mt * 16 + r0) * 64 + col;
                st[0]          = acc[mt][j][0];
                st[1]          = acc[mt][j][1];
                st[8 * 64]     = acc[mt][j][2];
                st[8 * 64 + 1] = acc[mt][j][3];
            }
    }
    __syncthreads();
    const bool is16 = (bx * 64) < nx;
    for (int i = tid; i < 2048; i += 256) {
        int row = i >> 4, c4 = (i & 15) << 2;
        int gr = by * 128 + row;
        if (gr >= M) continue;
        float4 v = *(float4*)(stage + row * 64 + c4);
        if (is16) {
            __half2 h0 = __floats2half2_rn(v.x, v.y);
            __half2 h1 = __floats2half2_rn(v.z, v.w);
            __half2* dp = (__half2*)(Ch + (size_t)gr * nx + bx * 64 + c4);
            dp[0] = h0; dp[1] = h1;
        } else {
            *(float4*)(Cf + (size_t)gr * nx + (bx * 64 - nx) + c4) = v;
        }
    }
}

// ---------------- layer 1: fused node kernel, 1 warp/head, half2 lane-pair channels ----------------
__global__ void __launch_bounds__(256) node1_fused_kernel(
    const float* __restrict__ att1, const float* __restrict__ b1)
{
    int n = blockIdx.x;
    int h = threadIdx.x >> 5, lane = threadIdx.x & 31;
    int beg = g_off[n], end = g_off[n + 1];
    int c0 = h * 64 + 2 * lane;          // this lane owns channels c0 and c0+1

    float xr0 = g_xr1[(size_t)n * 512 + c0];
    float xr1 = g_xr1[(size_t)n * 512 + c0 + 1];
    float at0 = att1[c0], at1 = att1[c0 + 1];

    float m = -CUDART_INF_F, ssum = 0.f, acc0 = 0.f, acc1 = 0.f;

    for (int r = beg; r < end; r += 32) {
        int cnt = min(32, end - r);
        int sidx = (lane < cnt) ? g_esrc[r + lane] : 0;
        for (int j = 0; j < cnt; j += 8) {
            float xa[8], xb[8], sc[8];
#pragma unroll
            for (int k = 0; k < 8; k++) {
                int sn = __shfl_sync(0xffffffffu, sidx, j + k);
                const __half2* p = (const __half2*)(g_xl1h + (size_t)sn * 512 + h * 64) + lane;
                bool valid = (j + k) < cnt;
                float2 f = valid ? __half22float2(*p) : make_float2(0.f, 0.f);
                xa[k] = f.x; xb[k] = f.y;
            }
#pragma unroll
            for (int k = 0; k < 8; k++) {
                float u = xa[k] + xr0; u = u > 0.f ? u : NEG_SLOPE * u;
                float v = xb[k] + xr1; v = v > 0.f ? v : NEG_SLOPE * v;
                sc[k] = at0 * u + at1 * v;
            }
#pragma unroll
            for (int o = 16; o; o >>= 1)
#pragma unroll
                for (int k = 0; k < 8; k++)
                    sc[k] += __shfl_xor_sync(0xffffffffu, sc[k], o);
            float mn = m;
#pragma unroll
            for (int k = 0; k < 8; k++)
                if ((j + k) < cnt) mn = fmaxf(mn, sc[k]);
            float scale = __expf(m - mn);
            float wsum = 0.f, a0 = 0.f, a1 = 0.f;
#pragma unroll
            for (int k = 0; k < 8; k++) {
                float w = ((j + k) < cnt) ? __expf(sc[k] - mn) : 0.f;
                wsum += w;
                a0 += w * xa[k];
                a1 += w * xb[k];
            }
            ssum = ssum * scale + wsum;
            acc0 = acc0 * scale + a0;
            acc1 = acc1 * scale + a1;
            m = mn;
        }
    }

    float inv = 1.f / (ssum + SM_EPS);
    float v0 = acc0 * inv + b1[c0];
    float v1 = acc1 * inv + b1[c0 + 1];
    v0 = v0 > 0.f ? v0 : __expf(v0) - 1.f;
    v1 = v1 > 0.f ? v1 : __expf(v1) - 1.f;
    size_t o0 = (size_t)n * HC1 + c0, o1 = o0 + 1;
    __nv_bfloat16 h0 = __float2bfloat16(v0), h1 = __float2bfloat16(v1);
    g_hhi[o0] = h0; g_hlo[o0] = __float2bfloat16(v0 - __bfloat162float(h0));
    g_hhi[o1] = h1; g_hlo[o1] = __float2bfloat16(v1 - __bfloat162float(h1));
}

// ---------------- layer 2: fused node kernel, 1 warp/node, half2 lane-pair channels ----------------
__global__ void __launch_bounds__(256) node2_fused_kernel(
    const float* __restrict__ att2, const float* __restrict__ b2,
    float* __restrict__ out)
{
    int n = blockIdx.x * 8 + (threadIdx.x >> 5);
    if (n >= N_NODES) return;
    int lane = threadIdx.x & 31;
    int beg = g_off[n], end = g_off[n + 1];
    int c0 = 2 * lane;

    float xr0 = g_xr2[(size_t)n * 64 + c0];
    float xr1 = g_xr2[(size_t)n * 64 + c0 + 1];
    float at0 = att2[c0], at1 = att2[c0 + 1];

    float m = -CUDART_INF_F, ssum = 0.f, acc0 = 0.f, acc1 = 0.f;

    for (int r = beg; r < end; r += 32) {
        int cnt = min(32, end - r);
        int sidx = (lane < cnt) ? g_esrc[r + lane] : 0;
        for (int j = 0; j < cnt; j += 8) {
            float xa[8], xb[8], sc[8];
#pragma unroll
            for (int k = 0; k < 8; k++) {
                int sn = __shfl_sync(0xffffffffu, sidx, j + k);
                const __half2* p = (const __half2*)(g_xl2h + (size_t)sn * 64) + lane;
                bool valid = (j + k) < cnt;
                float2 f = valid ? __half22float2(*p) : make_float2(0.f, 0.f);
                xa[k] = f.x; xb[k] = f.y;
            }
#pragma unroll
            for (int k = 0; k < 8; k++) {
                float u = xa[k] + xr0; u = u > 0.f ? u : NEG_SLOPE * u;
                float v = xb[k] + xr1; v = v > 0.f ? v : NEG_SLOPE * v;
                sc[k] = at0 * u + at1 * v;
            }
#pragma unroll
            for (int o = 16; o; o >>= 1)
#pragma unroll
                for (int k = 0; k < 8; k++)
                    sc[k] += __shfl_xor_sync(0xffffffffu, sc[k], o);
            float mn = m;
#pragma unroll
            for (int k = 0; k < 8; k++)
                if ((j + k) < cnt) mn = fmaxf(mn, sc[k]);
            float scale = __expf(m - mn);
            float wsum = 0.f, a0 = 0.f, a1 = 0.f;
#pragma unroll
            for (int k = 0; k < 8; k++) {
                float w = ((j + k) < cnt) ? __expf(sc[k] - mn) : 0.f;
                wsum += w;
                a0 += w * xa[k];
                a1 += w * xb[k];
            }
            ssum = ssum * scale + wsum;
            acc0 = acc0 * scale + a0;
            acc1 = acc1 * scale + a1;
            m = mn;
        }
    }

    float inv = 1.f / (ssum + SM_EPS);
    out[(size_t)n * NCLS + c0]     = acc0 * inv + b2[c0];
    out[(size_t)n * NCLS + c0 + 1] = acc1 * inv + b2[c0 + 1];
}

// ---------------- launch ----------------
extern "C" void kernel_launch(void* const* d_in, const int* in_sizes, int n_in,
                              void* d_out, int out_size)
{
    (void)in_sizes; (void)n_in; (void)out_size;
    const float* x    = (const float*)d_in[0];
    const int*   ei   = (const int*)d_in[1];
    const int*   src  = ei;
    const int*   dst  = ei + N_EDGES;
    const float* Wl1  = (const float*)d_in[2];
    const float* Wr1  = (const float*)d_in[3];
    const float* att1 = (const float*)d_in[4];
    const float* b1   = (const float*)d_in[5];
    const float* Wl2  = (const float*)d_in[6];
    const float* Wr2  = (const float*)d_in[7];
    const float* att2 = (const float*)d_in[8];
    const float* b2   = (const float*)d_in[9];
    float* out = (float*)d_out;

    cudaFuncSetAttribute(gemm_mma_kernel, cudaFuncAttributeMaxDynamicSharedMemorySize, SM_TOT);

    void *p_deg, *p_xl1h, *p_xr1, *p_xl2h, *p_xr2;
    void *p_xhi, *p_xlo, *p_hhi, *p_hlo, *p_w1h, *p_w1l, *p_w2h, *p_w2l;
    cudaGetSymbolAddress(&p_deg, g_deg);
    cudaGetSymbolAddress(&p_xl1h, g_xl1h);
    cudaGetSymbolAddress(&p_xr1, g_xr1);
    cudaGetSymbolAddress(&p_xl2h, g_xl2h);
    cudaGetSymbolAddress(&p_xr2, g_xr2);
    cudaGetSymbolAddress(&p_xhi, g_xhi);
    cudaGetSymbolAddress(&p_xlo, g_xlo);
    cudaGetSymbolAddress(&p_hhi, g_hhi);
    cudaGetSymbolAddress(&p_hlo, g_hlo);
    cudaGetSymbolAddress(&p_w1h, g_wt1hi);
    cudaGetSymbolAddress(&p_w1l, g_wt1lo);
    cudaGetSymbolAddress(&p_w2h, g_wt2hi);
    cudaGetSymbolAddress(&p_w2l, g_wt2lo);

    // CSR build (g_esrc = CSR-ordered src ids)
    cudaMemsetAsync(p_deg, 0, N_NODES * sizeof(int), 0);
    hist_kernel<<<(N_EDGES + 255) / 256, 256>>>(dst);
    scan_kernel<<<1, 1024>>>();
    scatter_kernel<<<(N_EDGES + 255) / 256, 256>>>(src, dst);

    // split x and weights (layer 1)
    split_kernel<<<(N_NODES * F_IN + 255) / 256, 256>>>(
        x, (__nv_bfloat16*)p_xhi, (__nv_bfloat16*)p_xlo, N_NODES * F_IN);
    wtsplit_kernel<<<(1024 * 256 + 255) / 256, 256>>>(
        Wl1, Wr1, 256, 512, (__nv_bfloat16*)p_w1h, (__nv_bfloat16*)p_w1l);

    // layer-1 projections: xl1 fp16 [N,512] + xr1 fp32 [N,512]
    {
        dim3 grid(1024 / 64, (N_NODES + 127) / 128);
        gemm_mma_kernel<<<grid, 256, SM_TOT>>>(
            N_NODES, 256, 512,
            (const __nv_bfloat16*)p_xhi, (const __nv_bfloat16*)p_xlo,
            (const __nv_bfloat16*)p_w1h, (const __nv_bfloat16*)p_w1l,
            (__half*)p_xl1h, (float*)p_xr1);
    }
    node1_fused_kernel<<<N_NODES, 256>>>(att1, b1);

    // weights (layer 2)
    wtsplit_kernel<<<(128 * 512 + 255) / 256, 256>>>(
        Wl2, Wr2, 512, 64, (__nv_bfloat16*)p_w2h, (__nv_bfloat16*)p_w2l);

    // layer-2 projections: xl2 fp16 [N,64] + xr2 fp32 [N,64]
    {
        dim3 grid(128 / 64, (N_NODES + 127) / 128);
        gemm_mma_kernel<<<grid, 256, SM_TOT>>>(
            N_NODES, 512, 64,
            (const __nv_bfloat16*)p_hhi, (const __nv_bfloat16*)p_hlo,
            (const __nv_bfloat16*)p_w2h, (const __nv_bfloat16*)p_w2l,
            (__half*)p_xl2h, (float*)p_xr2);
    }
    node2_fused_kernel<<<(N_NODES + 31) / 8 / 4 * 4, 256>>>(att2, b2, out);
}

// round 13
// speedup vs baseline: 1.0040x; 1.0040x over previous
#include <cuda_runtime.h>
#include <cuda_bf16.h>
#include <math_constants.h>
#include <cstdint>

// ---------------- problem constants ----------------
#define N_NODES 20000
#define N_EDGES 320000
#define F_IN    256
#define HIDC    64
#define HEADS   8
#define NCLS    64
#define HC1     (HEADS*HIDC)      // 512
#define NEG_SLOPE 0.2f
#define SM_EPS  1e-16f

typedef unsigned long long u64;

// ---------------- scratch (static device globals; no allocs) ----------------
__device__ float g_xlr1[(size_t)N_NODES * 1024];   // [N][xl1(512) | xr1(512)]
__device__ float g_xlr2[(size_t)N_NODES * 128];    // [N][xl2(64) | xr2(64)]
__device__ int   g_deg[N_NODES];
__device__ int   g_off[N_NODES + 1];
__device__ int   g_cur[N_NODES];
__device__ int   g_esrc[N_EDGES];                  // CSR-ordered source node ids

// bf16 split operands
__device__ __nv_bfloat16 g_xhi[(size_t)N_NODES * F_IN];
__device__ __nv_bfloat16 g_xlo[(size_t)N_NODES * F_IN];
__device__ __nv_bfloat16 g_hhi[(size_t)N_NODES * HC1];   // written by node1 epilogue
__device__ __nv_bfloat16 g_hlo[(size_t)N_NODES * HC1];
__device__ __nv_bfloat16 g_wt1hi[1024 * 256];   // [Ntot=1024][K=256] (W^T, K-contig)
__device__ __nv_bfloat16 g_wt1lo[1024 * 256];
__device__ __nv_bfloat16 g_wt2hi[128 * 512];    // [Ntot=128][K=512]
__device__ __nv_bfloat16 g_wt2lo[128 * 512];

// ---------------- helpers ----------------
__device__ __forceinline__ uint32_t smem_u32(const void* p) {
    uint32_t a;
    asm("{ .reg .u64 t; cvta.to.shared.u64 t, %1; cvt.u32.u64 %0, t; }" : "=r"(a) : "l"(p));
    return a;
}
#define SWZ128(o) ((o) ^ (((o) >> 3) & 0x70))

__device__ __forceinline__ void cp16(uint32_t dst, const void* src) {
    asm volatile("cp.async.cg.shared.global [%0], [%1], 16;" :: "r"(dst), "l"(src));
}
__device__ __forceinline__ void cp_commit() {
    asm volatile("cp.async.commit_group;" ::: "memory");
}
template <int N>
__device__ __forceinline__ void cp_wait() {
    asm volatile("cp.async.wait_group %0;" :: "n"(N) : "memory");
}

__device__ __forceinline__ void ldmx4(uint32_t* r, uint32_t addr) {
    asm volatile("ldmatrix.sync.aligned.m8n8.x4.shared.b16 {%0,%1,%2,%3}, [%4];"
                 : "=r"(r[0]), "=r"(r[1]), "=r"(r[2]), "=r"(r[3]) : "r"(addr));
}
__device__ __forceinline__ void mma16816(float* c, const uint32_t* a, uint32_t b0, uint32_t b1) {
    asm volatile("mma.sync.aligned.m16n8k16.row.col.f32.bf16.bf16.f32 "
                 "{%0,%1,%2,%3}, {%4,%5,%6,%7}, {%8,%9}, {%0,%1,%2,%3};"
                 : "+f"(c[0]), "+f"(c[1]), "+f"(c[2]), "+f"(c[3])
                 : "r"(a[0]), "r"(a[1]), "r"(a[2]), "r"(a[3]), "r"(b0), "r"(b1));
}

// ---------------- fused prep: hist | split(x) | wtsplit1 | wtsplit2 ----------------
// block ranges: hist [0,1250), split x [1250,21250), wt1 [21250,22274), wt2 [22274,22530)
#define PREP_HIST_BLKS  1250
#define PREP_SPLIT_BLKS 20000   // N_NODES*F_IN / 256 = 5,120,000 / 256
#define PREP_WT1_BLKS   1024
#define PREP_WT2_BLKS   256
#define PREP_TOTAL (PREP_HIST_BLKS + PREP_SPLIT_BLKS + PREP_WT1_BLKS + PREP_WT2_BLKS)

__global__ void __launch_bounds__(256) prep_kernel(
    const int* __restrict__ dst, const float* __restrict__ x,
    const float* __restrict__ Wl1, const float* __restrict__ Wr1,
    const float* __restrict__ Wl2, const float* __restrict__ Wr2)
{
    int b = blockIdx.x;
    if (b < PREP_HIST_BLKS) {
        int e = b * 256 + threadIdx.x;
        if (e < N_EDGES) atomicAdd(&g_deg[dst[e]], 1);
    } else if (b < PREP_HIST_BLKS + PREP_SPLIT_BLKS) {
        int i = (b - PREP_HIST_BLKS) * 256 + threadIdx.x;
        // i < 5,120,000 by construction
        float v = x[i];
        __nv_bfloat16 h = __float2bfloat16(v);
        g_xhi[i] = h;
        g_xlo[i] = __float2bfloat16(v - __bfloat162float(h));
    } else if (b < PREP_HIST_BLKS + PREP_SPLIT_BLKS + PREP_WT1_BLKS) {
        int i = (b - PREP_HIST_BLKS - PREP_SPLIT_BLKS) * 256 + threadIdx.x;
        // Wt1 [1024][256]: row n = col n of Wl1 (n<512) else Wr1
        int n = i >> 8, k = i & 255;
        float v = (n < 512) ? Wl1[(size_t)k * 512 + n] : Wr1[(size_t)k * 512 + (n - 512)];
        __nv_bfloat16 h = __float2bfloat16(v);
        g_wt1hi[i] = h;
        g_wt1lo[i] = __float2bfloat16(v - __bfloat162float(h));
    } else {
        int i = (b - PREP_HIST_BLKS - PREP_SPLIT_BLKS - PREP_WT1_BLKS) * 256 + threadIdx.x;
        // Wt2 [128][512]: row n = col n of Wl2 (n<64) else Wr2
        int n = i >> 9, k = i & 511;
        float v = (n < 64) ? Wl2[(size_t)k * 64 + n] : Wr2[(size_t)k * 64 + (n - 64)];
        __nv_bfloat16 h = __float2bfloat16(v);
        g_wt2hi[i] = h;
        g_wt2lo[i] = __float2bfloat16(v - __bfloat162float(h));
    }
}

// ---------------- CSR scan + scatter ----------------
__global__ void scan_kernel() {
    __shared__ int sums[1024];
    const int CH = (N_NODES + 1023) / 1024;
    int t = threadIdx.x;
    int base = t * CH;
    int s = 0;
    for (int i = 0; i < CH; i++) {
        int idx = base + i;
        if (idx < N_NODES) s += g_deg[idx];
    }
    sums[t] = s;
    __syncthreads();
    for (int d = 1; d < 1024; d <<= 1) {
        int v = (t >= d) ? sums[t - d] : 0;
        __syncthreads();
        sums[t] += v;
        __syncthreads();
    }
    int pre = (t == 0) ? 0 : sums[t - 1];
    for (int i = 0; i < CH; i++) {
        int idx = base + i;
        if (idx < N_NODES) {
            g_off[idx] = pre;
            g_cur[idx] = pre;
            pre += g_deg[idx];
        }
    }
    if (t == 0) g_off[N_NODES] = sums[1023];
}

__global__ void scatter_kernel(const int* __restrict__ src, const int* __restrict__ dst) {
    int e = blockIdx.x * blockDim.x + threadIdx.x;
    if (e < N_EDGES) {
        int p = atomicAdd(&g_cur[dst[e]], 1);
        g_esrc[p] = src[e];
    }
}

// ---------------- mma.sync split-bf16 GEMM, cp.async double-buffered ----------------
#define BUF_AHI 0
#define BUF_ALO 16384
#define BUF_BHI 32768
#define BUF_BLO 40960
#define BUF_SZ  49152
#define SM_TOT  (2 * BUF_SZ)

__global__ void __launch_bounds__(256) gemm_mma_kernel(
    int M, int K, int ldc,
    const __nv_bfloat16* __restrict__ Ahi, const __nv_bfloat16* __restrict__ Alo,
    const __nv_bfloat16* __restrict__ Bhi, const __nv_bfloat16* __restrict__ Blo,
    float* __restrict__ C)
{
    extern __shared__ char smem[];
    uint32_t sb = smem_u32(smem);
    const int tid = threadIdx.x, wid = tid >> 5, lane = tid & 31;
    const int by = blockIdx.y, bx = blockIdx.x;
    const int warpM = wid & 3, warpN = wid >> 2;

    float acc[2][4][4];
#pragma unroll
    for (int a = 0; a < 2; a++)
#pragma unroll
        for (int b = 0; b < 4; b++)
#pragma unroll
            for (int c = 0; c < 4; c++) acc[a][b][c] = 0.f;

    const int nchunks = K >> 6;

    auto issue = [&](int ch) {
        uint32_t buf = sb + (uint32_t)(ch & 1) * BUF_SZ;
        int k0 = ch << 6;
#pragma unroll
        for (int it = 0; it < 4; it++) {
            int i = tid + 256 * it;
            int row = i >> 3, g = (i & 7) << 3;
            int gr = by * 128 + row;
            if (gr >= M) gr = M - 1;
            uint32_t so = SWZ128(row * 128 + g * 2);
            cp16(buf + BUF_AHI + so, Ahi + (size_t)gr * K + k0 + g);
            cp16(buf + BUF_ALO + so, Alo + (size_t)gr * K + k0 + g);
        }
#pragma unroll
        for (int it = 0; it < 2; it++) {
            int i = tid + 256 * it;
            int row = i >> 3, g = (i & 7) << 3;
            int gn = bx * 64 + row;
            uint32_t so = SWZ128(row * 128 + g * 2);
            cp16(buf + BUF_BHI + so, Bhi + (size_t)gn * K + k0 + g);
            cp16(buf + BUF_BLO + so, Blo + (size_t)gn * K + k0 + g);
        }
        cp_commit();
    };

    issue(0);
    for (int ch = 0; ch < nchunks; ch++) {
        if (ch + 1 < nchunks) {
            issue(ch + 1);
            cp_wait<1>();
        } else {
            cp_wait<0>();
        }
        __syncthreads();

        uint32_t buf = sb + (uint32_t)(ch & 1) * BUF_SZ;
#pragma unroll
        for (int ks = 0; ks < 4; ks++) {
            uint32_t ahi[2][4], alo[2][4], bhi[2][4], blo[2][4];
            int colb = ks * 32 + (lane >> 4) * 16;
#pragma unroll
            for (int mt = 0; mt < 2; mt++) {
                uint32_t off = SWZ128((warpM * 32 + mt * 16 + (lane & 15)) * 128 + colb);
                ldmx4(ahi[mt], buf + BUF_AHI + off);
                ldmx4(alo[mt], buf + BUF_ALO + off);
            }
#pragma unroll
            for (int nt = 0; nt < 2; nt++) {
                uint32_t off = SWZ128((warpN * 32 + nt * 16 + (lane & 15)) * 128 + colb);
                ldmx4(bhi[nt], buf + BUF_BHI + off);
                ldmx4(blo[nt], buf + BUF_BLO + off);
            }
#pragma unroll
            for (int mt = 0; mt < 2; mt++)
#pragma unroll
                for (int nt = 0; nt < 2; nt++)
#pragma unroll
                    for (int hf = 0; hf < 2; hf++) {
                        float* c = acc[mt][nt * 2 + hf];
                        mma16816(c, ahi[mt], bhi[nt][hf], bhi[nt][hf + 2]);
                        mma16816(c, ahi[mt], blo[nt][hf], blo[nt][hf + 2]);
                        mma16816(c, alo[mt], bhi[nt][hf], bhi[nt][hf + 2]);
                    }
        }
        __syncthreads();
    }

    float* stage = (float*)smem;
    {
        int r0 = lane >> 2, cb = (lane & 3) * 2;
#pragma unroll
        for (int mt = 0; mt < 2; mt++)
#pragma unroll
            for (int j = 0; j < 4; j++) {
                int col = warpN * 32 + (j >> 1) * 16 + (j & 1) * 8 + cb;
                float* st = stage + (warpM * 32 + mt * 16 + r0) * 64 + col;
                st[0]          = acc[mt][j][0];
                st[1]          = acc[mt][j][1];
                st[8 * 64]     = acc[mt][j][2];
                st[8 * 64 + 1] = acc[mt][j][3];
            }
    }
    __syncthreads();
    for (int i = tid; i < 2048; i += 256) {
        int row = i >> 4, c4 = (i & 15) << 2;
        int gr = by * 128 + row;
        if (gr < M)
            *(float4*)(C + (size_t)gr * ldc + bx * 64 + c4) = *(float4*)(stage + row * 64 + c4);
    }
}

// ---------------- layer 1: fused node kernel, 1 warp/head, lane-parallel indices ----------------
__global__ void __launch_bounds__(256) node1_fused_kernel(
    const float* __restrict__ att1, const float* __restrict__ b1)
{
    int n = blockIdx.x;
    int h = threadIdx.x >> 5, lane = threadIdx.x & 31;
    int beg = g_off[n], end = g_off[n + 1];
    int c0 = h * 64 + lane;

    float xr0 = g_xlr1[(size_t)n * 1024 + 512 + c0];
    float xr1 = g_xlr1[(size_t)n * 1024 + 512 + c0 + 32];
    float at0 = att1[c0], at1 = att1[c0 + 32];

    float m = -CUDART_INF_F, ssum = 0.f, acc0 = 0.f, acc1 = 0.f;

    for (int r = beg; r < end; r += 32) {
        int cnt = min(32, end - r);
        int sidx = (lane < cnt) ? g_esrc[r + lane] : 0;
        for (int j = 0; j < cnt; j += 8) {
            float xa[8], xb[8], sc[8];
#pragma unroll
            for (int k = 0; k < 8; k++) {
                int sn = __shfl_sync(0xffffffffu, sidx, j + k);
                const float* p = g_xlr1 + (size_t)sn * 1024 + h * 64;
                bool valid = (j + k) < cnt;
                xa[k] = valid ? p[lane] : 0.f;
                xb[k] = valid ? p[lane + 32] : 0.f;
            }
#pragma unroll
            for (int k = 0; k < 8; k++) {
                float u = xa[k] + xr0; u = u > 0.f ? u : NEG_SLOPE * u;
                float v = xb[k] + xr1; v = v > 0.f ? v : NEG_SLOPE * v;
                sc[k] = at0 * u + at1 * v;
            }
#pragma unroll
            for (int o = 16; o; o >>= 1)
#pragma unroll
                for (int k = 0; k < 8; k++)
                    sc[k] += __shfl_xor_sync(0xffffffffu, sc[k], o);
            float mn = m;
#pragma unroll
            for (int k = 0; k < 8; k++)
                if ((j + k) < cnt) mn = fmaxf(mn, sc[k]);
            float scale = __expf(m - mn);
            float wsum = 0.f, a0 = 0.f, a1 = 0.f;
#pragma unroll
            for (int k = 0; k < 8; k++) {
                float w = ((j + k) < cnt) ? __expf(sc[k] - mn) : 0.f;
                wsum += w;
                a0 += w * xa[k];
                a1 += w * xb[k];
            }
            ssum = ssum * scale + wsum;
            acc0 = acc0 * scale + a0;
            acc1 = acc1 * scale + a1;
            m = mn;
        }
    }

    float inv = 1.f / (ssum + SM_EPS);
    float v0 = acc0 * inv + b1[c0];
    float v1 = acc1 * inv + b1[c0 + 32];
    v0 = v0 > 0.f ? v0 : __expf(v0) - 1.f;
    v1 = v1 > 0.f ? v1 : __expf(v1) - 1.f;
    size_t o0 = (size_t)n * HC1 + c0, o1 = o0 + 32;
    __nv_bfloat16 h0 = __float2bfloat16(v0), h1 = __float2bfloat16(v1);
    g_hhi[o0] = h0; g_hlo[o0] = __float2bfloat16(v0 - __bfloat162float(h0));
    g_hhi[o1] = h1; g_hlo[o1] = __float2bfloat16(v1 - __bfloat162float(h1));
}

// ---------------- layer 2: fused node kernel, 1 warp/node ----------------
__global__ void __launch_bounds__(256) node2_fused_kernel(
    const float* __restrict__ att2, const float* __restrict__ b2,
    float* __restrict__ out)
{
    int n = blockIdx.x * 8 + (threadIdx.x >> 5);
    if (n >= N_NODES) return;
    int lane = threadIdx.x & 31;
    int beg = g_off[n], end = g_off[n + 1];

    float xr0 = g_xlr2[(size_t)n * 128 + 64 + lane];
    float xr1 = g_xlr2[(size_t)n * 128 + 64 + lane + 32];
    float at0 = att2[lane], at1 = att2[lane + 32];

    float m = -CUDART_INF_F, ssum = 0.f, acc0 = 0.f, acc1 = 0.f;

    for (int r = beg; r < end; r += 32) {
        int cnt = min(32, end - r);
        int sidx = (lane < cnt) ? g_esrc[r + lane] : 0;
        for (int j = 0; j < cnt; j += 8) {
            float xa[8], xb[8], sc[8];
#pragma unroll
            for (int k = 0; k < 8; k++) {
                int sn = __shfl_sync(0xffffffffu, sidx, j + k);
                const float* p = g_xlr2 + (size_t)sn * 128;
                bool valid = (j + k) < cnt;
                xa[k] = valid ? p[lane] : 0.f;
                xb[k] = valid ? p[lane + 32] : 0.f;
            }
#pragma unroll
            for (int k = 0; k < 8; k++) {
                float u = xa[k] + xr0; u = u > 0.f ? u : NEG_SLOPE * u;
                float v = xb[k] + xr1; v = v > 0.f ? v : NEG_SLOPE * v;
                sc[k] = at0 * u + at1 * v;
            }
#pragma unroll
            for (int o = 16; o; o >>= 1)
#pragma unroll
                for (int k = 0; k < 8; k++)
                    sc[k] += __shfl_xor_sync(0xffffffffu, sc[k], o);
            float mn = m;
#pragma unroll
            for (int k = 0; k < 8; k++)
                if ((j + k) < cnt) mn = fmaxf(mn, sc[k]);
            float scale = __expf(m - mn);
            float wsum = 0.f, a0 = 0.f, a1 = 0.f;
#pragma unroll
            for (int k = 0; k < 8; k++) {
                float w = ((j + k) < cnt) ? __expf(sc[k] - mn) : 0.f;
                wsum += w;
                a0 += w * xa[k];
                a1 += w * xb[k];
            }
            ssum = ssum * scale + wsum;
            acc0 = acc0 * scale + a0;
            acc1 = acc1 * scale + a1;
            m = mn;
        }
    }

    float inv = 1.f / (ssum + SM_EPS);
    out[(size_t)n * NCLS + lane]      = acc0 * inv + b2[lane];
    out[(size_t)n * NCLS + lane + 32] = acc1 * inv + b2[lane + 32];
}

// ---------------- launch ----------------
extern "C" void kernel_launch(void* const* d_in, const int* in_sizes, int n_in,
                              void* d_out, int out_size)
{
    (void)in_sizes; (void)n_in; (void)out_size;
    const float* x    = (const float*)d_in[0];
    const int*   ei   = (const int*)d_in[1];
    const int*   src  = ei;
    const int*   dst  = ei + N_EDGES;
    const float* Wl1  = (const float*)d_in[2];
    const float* Wr1  = (const float*)d_in[3];
    const float* att1 = (const float*)d_in[4];
    const float* b1   = (const float*)d_in[5];
    const float* Wl2  = (const float*)d_in[6];
    const float* Wr2  = (const float*)d_in[7];
    const float* att2 = (const float*)d_in[8];
    const float* b2   = (const float*)d_in[9];
    float* out = (float*)d_out;

    cudaFuncSetAttribute(gemm_mma_kernel, cudaFuncAttributeMaxDynamicSharedMemorySize, SM_TOT);

    void *p_deg, *p_xlr1, *p_xlr2;
    void *p_xhi, *p_xlo, *p_hhi, *p_hlo, *p_w1h, *p_w1l, *p_w2h, *p_w2l;
    cudaGetSymbolAddress(&p_deg, g_deg);
    cudaGetSymbolAddress(&p_xlr1, g_xlr1);
    cudaGetSymbolAddress(&p_xlr2, g_xlr2);
    cudaGetSymbolAddress(&p_xhi, g_xhi);
    cudaGetSymbolAddress(&p_xlo, g_xlo);
    cudaGetSymbolAddress(&p_hhi, g_hhi);
    cudaGetSymbolAddress(&p_hlo, g_hlo);
    cudaGetSymbolAddress(&p_w1h, g_wt1hi);
    cudaGetSymbolAddress(&p_w1l, g_wt1lo);
    cudaGetSymbolAddress(&p_w2h, g_wt2hi);
    cudaGetSymbolAddress(&p_w2l, g_wt2lo);

    // (1) zero degree histogram
    cudaMemsetAsync(p_deg, 0, N_NODES * sizeof(int), 0);
    // (2) fused prep: hist | x-split | wt1 transpose-split | wt2 transpose-split
    prep_kernel<<<PREP_TOTAL, 256>>>(dst, x, Wl1, Wr1, Wl2, Wr2);
    // (3) CSR scan, (4) scatter (g_esrc = CSR-ordered src ids)
    scan_kernel<<<1, 1024>>>();
    scatter_kernel<<<(N_EDGES + 255) / 256, 256>>>(src, dst);

    // (5) layer-1 projections: g_xlr1 [N,1024]  <-- profiled slot
    {
        dim3 grid(1024 / 64, (N_NODES + 127) / 128);
        gemm_mma_kernel<<<grid, 256, SM_TOT>>>(
            N_NODES, 256, 1024,
            (const __nv_bfloat16*)p_xhi, (const __nv_bfloat16*)p_xlo,
            (const __nv_bfloat16*)p_w1h, (const __nv_bfloat16*)p_w1l,
            (float*)p_xlr1);
    }
    // (6) layer-1 node phase
    node1_fused_kernel<<<N_NODES, 256>>>(att1, b1);

    // (7) layer-2 projections: g_xlr2 [N,128]
    {
        dim3 grid(128 / 64, (N_NODES + 127) / 128);
        gemm_mma_kernel<<<grid, 256, SM_TOT>>>(
            N_NODES, 512, 128,
            (const __nv_bfloat16*)p_hhi, (const __nv_bfloat16*)p_hlo,
            (const __nv_bfloat16*)p_w2h, (const __nv_bfloat16*)p_w2l,
            (float*)p_xlr2);
    }
    // (8) layer-2 node phase -> output
    node2_fused_kernel<<<(N_NODES + 7) / 8, 256>>>(att2, b2, out);
}